// round 2
// baseline (speedup 1.0000x reference)
#include <cuda_runtime.h>
#include <cstdint>

#define BATCH     131072
#define NF        64

// One warp per (user,item) row.
// Lane l loads p[2l..2l+1] and q[2l..2l+1] as float2 (coalesced 256B per row),
// computes partial dot, butterfly-reduces, writes features as float2.
__global__ __launch_bounds__(256) void svd_predict_kernel(
    const int*   __restrict__ user_item,   // [BATCH, 2]
    const float* __restrict__ pu,          // [N_USERS, 64]
    const float* __restrict__ qi,          // [N_ITEMS, 64]
    const float* __restrict__ bu,          // [N_USERS]
    const float* __restrict__ bi,          // [N_ITEMS]
    const float* __restrict__ gmean,       // [1]
    float*       __restrict__ out)         // [BATCH] pred ++ [BATCH,128] feat
{
    const int warp_id = (blockIdx.x * blockDim.x + threadIdx.x) >> 5;
    const int lane    = threadIdx.x & 31;
    if (warp_id >= BATCH) return;

    // Both ids for this row (8B broadcast load — conflict-free)
    const int2 ids = __ldg(((const int2*)user_item) + warp_id);
    const int uid = ids.x;
    const int iid = ids.y;

    const float2* __restrict__ prow = (const float2*)(pu + (size_t)uid * NF);
    const float2* __restrict__ qrow = (const float2*)(qi + (size_t)iid * NF);

    const float2 p = __ldg(prow + lane);
    const float2 q = __ldg(qrow + lane);

    float partial = p.x * q.x + p.y * q.y;
    #pragma unroll
    for (int off = 16; off > 0; off >>= 1)
        partial += __shfl_xor_sync(0xffffffffu, partial, off);

    // Feature row: [p (64) | q (64)] — 512B coalesced via float2 stores
    float2* __restrict__ frow = (float2*)(out + (size_t)BATCH + (size_t)warp_id * (2 * NF));
    frow[lane]      = p;
    frow[lane + 32] = q;

    if (lane == 0) {
        float v = gmean[0] + __ldg(bu + uid) + __ldg(bi + iid) + partial;
        v = fminf(fmaxf(v, 1.0f), 5.0f);
        out[warp_id] = v;
    }
}

extern "C" void kernel_launch(void* const* d_in, const int* in_sizes, int n_in,
                              void* d_out, int out_size)
{
    const int*   user_item = (const int*)  d_in[0];
    const float* pu        = (const float*)d_in[1];
    const float* qi        = (const float*)d_in[2];
    const float* bu        = (const float*)d_in[3];
    const float* bi        = (const float*)d_in[4];
    const float* gmean     = (const float*)d_in[5];
    float*       out       = (float*)d_out;

    // 256 threads/block = 8 warps = 8 rows per block
    const int rows_per_block = 256 / 32;
    const int grid = (BATCH + rows_per_block - 1) / rows_per_block;
    svd_predict_kernel<<<grid, 256>>>(user_item, pu, qi, bu, bi, gmean, out);
}

// round 3
// speedup vs baseline: 1.4396x; 1.4396x over previous
#include <cuda_runtime.h>
#include <cstdint>

#define BATCH 131072
#define NF    64
#define RPW   8   // rows per warp (4 pairs; 16-lane subwarp per row)

__global__ __launch_bounds__(256) void svd_predict_kernel(
    const int*   __restrict__ user_item,   // [BATCH, 2]
    const float* __restrict__ pu,          // [N_USERS, 64]
    const float* __restrict__ qi,          // [N_ITEMS, 64]
    const float* __restrict__ bu,          // [N_USERS]
    const float* __restrict__ bi,          // [N_ITEMS]
    const float* __restrict__ gmean,       // [1]
    float*       __restrict__ out)         // [BATCH] pred ++ [BATCH,128] feat
{
    const int warp_id = (blockIdx.x * blockDim.x + threadIdx.x) >> 5;
    const int lane    = threadIdx.x & 31;
    const int half    = lane >> 4;        // which row of the pair
    const int sub     = lane & 15;        // lane within 16-lane subwarp
    const int row0    = warp_id * RPW + half;   // rows: row0 + 2*i, i=0..3

    // ---- batch all index loads (1MB array, L1/L2 resident) ----
    int2 ids[4];
    #pragma unroll
    for (int i = 0; i < 4; ++i)
        ids[i] = __ldg(((const int2*)user_item) + row0 + 2 * i);

    // ---- issue all 8 independent 16B embedding loads (max MLP) ----
    float4 p[4], q[4];
    #pragma unroll
    for (int i = 0; i < 4; ++i) {
        p[i] = __ldg(((const float4*)(pu + (size_t)ids[i].x * NF)) + sub);
        q[i] = __ldg(((const float4*)(qi + (size_t)ids[i].y * NF)) + sub);
    }

    // ---- bias loads (only sub==0 needs them), also batched ----
    float bsum[4];
    #pragma unroll
    for (int i = 0; i < 4; ++i)
        if (sub == 0)
            bsum[i] = __ldg(bu + ids[i].x) + __ldg(bi + ids[i].y);

    const float gm = __ldg(gmean);

    // ---- per-row: dot, reduce over 16 lanes, store ----
    #pragma unroll
    for (int i = 0; i < 4; ++i) {
        const int row = row0 + 2 * i;

        float partial = p[i].x * q[i].x + p[i].y * q[i].y
                      + p[i].z * q[i].z + p[i].w * q[i].w;
        #pragma unroll
        for (int off = 8; off > 0; off >>= 1)
            partial += __shfl_xor_sync(0xffffffffu, partial, off, 16);

        // features: [p(64) | q(64)] = 32 float4, streaming stores
        float4* frow = (float4*)(out + (size_t)BATCH + (size_t)row * (2 * NF));
        __stcs(frow + sub,      p[i]);
        __stcs(frow + sub + 16, q[i]);

        if (sub == 0) {
            float v = gm + bsum[i] + partial;
            v = fminf(fmaxf(v, 1.0f), 5.0f);
            __stcs(out + row, v);
        }
    }
}

extern "C" void kernel_launch(void* const* d_in, const int* in_sizes, int n_in,
                              void* d_out, int out_size)
{
    const int*   user_item = (const int*)  d_in[0];
    const float* pu        = (const float*)d_in[1];
    const float* qi        = (const float*)d_in[2];
    const float* bu        = (const float*)d_in[3];
    const float* bi        = (const float*)d_in[4];
    const float* gmean     = (const float*)d_in[5];
    float*       out       = (float*)d_out;

    // 256 threads = 8 warps = 64 rows per block
    const int rows_per_block = (256 / 32) * RPW;
    const int grid = (BATCH + rows_per_block - 1) / rows_per_block;
    svd_predict_kernel<<<grid, 256>>>(user_item, pu, qi, bu, bi, gmean, out);
}